// round 2
// baseline (speedup 1.0000x reference)
#include <cuda_runtime.h>
#include <cuda_bf16.h>
#include <cstdint>
#include <math.h>

#define BB 2
#define NN 2048
#define CC 384
#define HH 6
#define DD 64
#define TCC 1152   // 3*C
#define MM 4096    // B*N

typedef __nv_bfloat16 bf16;

// ---------------- device scratch (static: no allocations allowed) ----------------
__device__ bf16   g_wqkv[TCC * CC];                    // w_qkv integer levels
__device__ bf16   g_wproj[CC * CC];                    // w_proj integer levels
__device__ bf16   g_q[BB * HH * NN * DD];              // q levels   [B,H,N,D]
__device__ bf16   g_k[BB * HH * NN * DD];              // k levels
__device__ bf16   g_v[BB * HH * NN * DD];              // v levels
__device__ int8_t g_s[(size_t)BB * HH * NN * NN];      // attn score levels (50MB)
__device__ bf16   g_o[(size_t)MM * CC];                // attn-out levels [B,N,C]

// ---------------- helpers ----------------
__device__ __forceinline__ float qlvl(float x, float inv_alpha) {
    float s = x * inv_alpha;
    s = fminf(fmaxf(s, -128.f), 127.f);
    return rintf(s);                 // round-half-to-even, matches jnp.round
}

__device__ __forceinline__ void mma16816(float* c, const uint32_t* a,
                                         uint32_t b0, uint32_t b1) {
    asm volatile(
        "mma.sync.aligned.m16n8k16.row.col.f32.bf16.bf16.f32 "
        "{%0,%1,%2,%3}, {%4,%5,%6,%7}, {%8,%9}, {%0,%1,%2,%3};\n"
        : "+f"(c[0]), "+f"(c[1]), "+f"(c[2]), "+f"(c[3])
        : "r"(a[0]), "r"(a[1]), "r"(a[2]), "r"(a[3]), "r"(b0), "r"(b1));
}

// ---------------- kernel 1: quantize weights to bf16 integer levels ----------------
__global__ void k_quant_w(const float* __restrict__ wqkv,
                          const float* __restrict__ wproj,
                          const float* __restrict__ a_qkv_w,
                          const float* __restrict__ a_proj_w) {
    float i1 = 1.f / a_qkv_w[0];
    float i2 = 1.f / a_proj_w[0];
    int i = blockIdx.x * 256 + threadIdx.x;
    if (i < TCC * CC) g_wqkv[i]  = __float2bfloat16(qlvl(wqkv[i], i1));
    if (i < CC * CC)  g_wproj[i] = __float2bfloat16(qlvl(wproj[i], i2));
}

// ---------------- kernel 2: QKV GEMM (M=4096, N=1152, K=384) ----------------
// CTA 128x128, BK=32, 8 warps (2 along M x 4 along N), warp tile 64x32.
__global__ __launch_bounds__(256) void k_qkv(
        const float* __restrict__ x,
        const float* __restrict__ a_qkv_a, const float* __restrict__ a_qkv_w,
        const float* __restrict__ a_q, const float* __restrict__ a_k,
        const float* __restrict__ a_v) {
    __shared__ bf16 sA[128][48];
    __shared__ bf16 sB[128][48];

    int tid = threadIdx.x, lane = tid & 31, wid = tid >> 5;
    int wm = wid & 1, wn = wid >> 1;
    int gr = lane >> 2, gc = (lane & 3) * 2;
    int m0 = blockIdx.x * 128, n0 = blockIdx.y * 128;
    float invaa = 1.f / a_qkv_a[0];

    float acc[4][4][4];
    #pragma unroll
    for (int i = 0; i < 4; i++)
        #pragma unroll
        for (int j = 0; j < 4; j++)
            #pragma unroll
            for (int c = 0; c < 4; c++) acc[i][j][c] = 0.f;

    for (int kt = 0; kt < 12; kt++) {
        // load + quantize x tile (128x32 fp32 -> bf16 levels)
        #pragma unroll
        for (int t = 0; t < 4; t++) {
            int idx = tid + t * 256;
            int r = idx >> 3, c4 = (idx & 7) * 4;
            float4 v = *(const float4*)&x[(size_t)(m0 + r) * CC + kt * 32 + c4];
            __nv_bfloat162 p0, p1;
            p0.x = __float2bfloat16(qlvl(v.x, invaa));
            p0.y = __float2bfloat16(qlvl(v.y, invaa));
            p1.x = __float2bfloat16(qlvl(v.z, invaa));
            p1.y = __float2bfloat16(qlvl(v.w, invaa));
            *(__nv_bfloat162*)&sA[r][c4] = p0;
            *(__nv_bfloat162*)&sA[r][c4 + 2] = p1;
        }
        // load w tile (128x32 bf16)
        #pragma unroll
        for (int t = 0; t < 2; t++) {
            int idx = tid + t * 256;
            int r = idx >> 2, c8 = (idx & 3) * 8;
            *(uint4*)&sB[r][c8] =
                *(const uint4*)&g_wqkv[(size_t)(n0 + r) * CC + kt * 32 + c8];
        }
        __syncthreads();
        #pragma unroll
        for (int ks = 0; ks < 2; ks++) {
            uint32_t af[4][4], bfr[4][2];
            #pragma unroll
            for (int i = 0; i < 4; i++) {
                int rb = wm * 64 + i * 16;
                af[i][0] = *(const uint32_t*)&sA[rb + gr][ks * 16 + gc];
                af[i][1] = *(const uint32_t*)&sA[rb + gr + 8][ks * 16 + gc];
                af[i][2] = *(const uint32_t*)&sA[rb + gr][ks * 16 + gc + 8];
                af[i][3] = *(const uint32_t*)&sA[rb + gr + 8][ks * 16 + gc + 8];
            }
            #pragma unroll
            for (int j = 0; j < 4; j++) {
                int nb = wn * 32 + j * 8;
                bfr[j][0] = *(const uint32_t*)&sB[nb + gr][ks * 16 + gc];
                bfr[j][1] = *(const uint32_t*)&sB[nb + gr][ks * 16 + gc + 8];
            }
            #pragma unroll
            for (int i = 0; i < 4; i++)
                #pragma unroll
                for (int j = 0; j < 4; j++)
                    mma16816(acc[i][j], af[i], bfr[j][0], bfr[j][1]);
        }
        __syncthreads();
    }

    // epilogue: scale, split into q/k/v, re-quantize, store as [B,H,N,D] levels
    int which = n0 / CC;  // tile fully inside one of q/k/v (384 = 3*128)
    const float* a3 = (which == 0) ? a_q : (which == 1 ? a_k : a_v);
    float inv3 = 1.f / a3[0];
    float sAB = a_qkv_a[0] * a_qkv_w[0];
    bf16* dst = (which == 0) ? g_q : (which == 1 ? g_k : g_v);
    int ncol0 = n0 - which * CC;
    #pragma unroll
    for (int i = 0; i < 4; i++)
        #pragma unroll
        for (int j = 0; j < 4; j++)
            #pragma unroll
            for (int c = 0; c < 4; c++) {
                int row = m0 + wm * 64 + i * 16 + gr + ((c >> 1) * 8);
                int col = ncol0 + wn * 32 + j * 8 + gc + (c & 1);
                int b = row >> 11, n = row & 2047;
                int h = col >> 6, d = col & 63;
                float lvl = qlvl(acc[i][j][c] * sAB, inv3);
                dst[(((size_t)(b * HH + h)) * NN + n) * DD + d] =
                    __float2bfloat16(lvl);
            }
}

// ---------------- kernel 3: fused attention per (b,h, 128-row tile) ----------------
__global__ __launch_bounds__(256) void k_attn(
        const float* __restrict__ a_q, const float* __restrict__ a_k,
        const float* __restrict__ a_attn, const float* __restrict__ a_attn2,
        const float* __restrict__ a_v, const float* __restrict__ a_proj_a) {
    __shared__ __align__(16) char su[36864];
    bf16(*sQ)[72] = (bf16(*)[72])su;                    // pass1: 128x64 (+pad)
    bf16(*sK)[72] = (bf16(*)[72])(su + 128 * 72 * 2);   // pass1: 128x64
    bf16(*sP)[72] = (bf16(*)[72])su;                    // pass2: 128x64
    bf16(*sV)[72] = (bf16(*)[72])(su + 128 * 72 * 2);   // pass2: 64x64 (transposed)
    __shared__ float lut[260];
    __shared__ int   redm[4][128];
    __shared__ float redl[4][128];
    __shared__ int   srm[128];
    __shared__ float srli[128];

    int tid = threadIdx.x, lane = tid & 31, wid = tid >> 5;
    int wm = wid & 1, wn = wid >> 1;
    int gr = lane >> 2, gc = (lane & 3) * 2;
    int bh = blockIdx.y;
    int rt0 = blockIdx.x * 128;

    float aat = a_attn[0];
    float fsc = a_q[0] * a_k[0] * 0.125f / aat;  // scale = D^-0.5 = 1/8

    for (int i = tid; i < 260; i += 256) lut[i] = expf(-(float)i * aat);

    // load Q tile (resident for pass 1)
    const bf16* qptr = g_q + ((size_t)bh * NN + rt0) * DD;
    #pragma unroll
    for (int t = 0; t < 4; t++) {
        int idx = tid + t * 256;
        int r = idx >> 3, c8 = (idx & 7) * 8;
        *(uint4*)&sQ[r][c8] = *(const uint4*)&qptr[(size_t)r * DD + c8];
    }

    int   tm[8];
    float tl[8];
    #pragma unroll
    for (int r = 0; r < 8; r++) { tm[r] = -300; tl[r] = 0.f; }

    size_t sbase = ((size_t)bh * NN + rt0) * NN;

    // ---------- pass 1: S = Q K^T, quantize, scratch store, online stats ----------
    for (int ct = 0; ct < 16; ct++) {
        const bf16* kptr = g_k + ((size_t)bh * NN + ct * 128) * DD;
        #pragma unroll
        for (int t = 0; t < 4; t++) {
            int idx = tid + t * 256;
            int r = idx >> 3, c8 = (idx & 7) * 8;
            *(uint4*)&sK[r][c8] = *(const uint4*)&kptr[(size_t)r * DD + c8];
        }
        __syncthreads();

        float acc[4][4][4];
        #pragma unroll
        for (int i = 0; i < 4; i++)
            #pragma unroll
            for (int j = 0; j < 4; j++)
                #pragma unroll
                for (int c = 0; c < 4; c++) acc[i][j][c] = 0.f;

        #pragma unroll
        for (int ks = 0; ks < 4; ks++) {
            uint32_t af[4][4], bfr[4][2];
            #pragma unroll
            for (int i = 0; i < 4; i++) {
                int rb = wm * 64 + i * 16;
                af[i][0] = *(const uint32_t*)&sQ[rb + gr][ks * 16 + gc];
                af[i][1] = *(const uint32_t*)&sQ[rb + gr + 8][ks * 16 + gc];
                af[i][2] = *(const uint32_t*)&sQ[rb + gr][ks * 16 + gc + 8];
                af[i][3] = *(const uint32_t*)&sQ[rb + gr + 8][ks * 16 + gc + 8];
            }
            #pragma unroll
            for (int j = 0; j < 4; j++) {
                int nb = wn * 32 + j * 8;
                bfr[j][0] = *(const uint32_t*)&sK[nb + gr][ks * 16 + gc];
                bfr[j][1] = *(const uint32_t*)&sK[nb + gr][ks * 16 + gc + 8];
            }
            #pragma unroll
            for (int i = 0; i < 4; i++)
                #pragma unroll
                for (int j = 0; j < 4; j++)
                    mma16816(acc[i][j], af[i], bfr[j][0], bfr[j][1]);
        }

        // quantize scores, update online (m,l), store int8 levels (2B packed)
        #pragma unroll
        for (int i = 0; i < 4; i++)
            #pragma unroll
            for (int j = 0; j < 4; j++)
                #pragma unroll
                for (int half = 0; half < 2; half++) {
                    float v0 = fminf(fmaxf(acc[i][j][half * 2] * fsc, -128.f), 127.f);
                    float v1 = fminf(fmaxf(acc[i][j][half * 2 + 1] * fsc, -128.f), 127.f);
                    int l0 = __float2int_rn(v0);
                    int l1 = __float2int_rn(v1);
                    int ri = i * 2 + half;
                    int mx = (l0 > l1) ? l0 : l1;
                    if (mx > tm[ri]) {
                        tl[ri] = tl[ri] * lut[min(mx - tm[ri], 259)];
                        tm[ri] = mx;
                    }
                    tl[ri] += lut[tm[ri] - l0] + lut[tm[ri] - l1];
                    int lr = wm * 64 + i * 16 + gr + half * 8;
                    int gcol = ct * 128 + wn * 32 + j * 8 + gc;
                    uint16_t pk = (uint16_t)((l0 & 0xff) | ((l1 & 0xff) << 8));
                    *(uint16_t*)&g_s[sbase + (size_t)lr * NN + gcol] = pk;
                }
        __syncthreads();
    }

    // ---------- reduce (m,l) across lanes and warps ----------
    #pragma unroll
    for (int ri = 0; ri < 8; ri++) {
        int m = tm[ri];
        float l = tl[ri];
        #pragma unroll
        for (int off = 1; off <= 2; off <<= 1) {
            int m2 = __shfl_xor_sync(0xffffffff, m, off);
            float l2 = __shfl_xor_sync(0xffffffff, l, off);
            if (m2 > m) { float t = l; l = l2; l2 = t; int t2 = m; m = m2; m2 = t2; }
            l += l2 * lut[min(m - m2, 259)];
        }
        if ((lane & 3) == 0) {
            int row = wm * 64 + (ri >> 1) * 16 + (ri & 1) * 8 + gr;
            redm[wn][row] = m;
            redl[wn][row] = l;
        }
    }
    __syncthreads();
    if (tid < 128) {
        int m = redm[0][tid];
        float l = redl[0][tid];
        #pragma unroll
        for (int w = 1; w < 4; w++) {
            int m2 = redm[w][tid];
            float l2 = redl[w][tid];
            if (m2 > m) { float t = l; l = l2; l2 = t; int t2 = m; m = m2; m2 = t2; }
            l += l2 * lut[min(m - m2, 259)];
        }
        srm[tid] = m;
        srli[tid] = 1.f / l;
    }
    __syncthreads();

    // ---------- pass 2: P = quant2(softmax), O += P V ----------
    float inva2 = 1.f / a_attn2[0];
    float acco[4][2][4];
    #pragma unroll
    for (int i = 0; i < 4; i++)
        #pragma unroll
        for (int j = 0; j < 2; j++)
            #pragma unroll
            for (int c = 0; c < 4; c++) acco[i][j][c] = 0.f;

    for (int ct2 = 0; ct2 < 32; ct2++) {
        // S levels tile (128x64 int8) -> P levels bf16 in smem
        const int8_t* sptr = g_s + sbase + ct2 * 64;
        #pragma unroll
        for (int t = 0; t < 2; t++) {
            int idx = tid + t * 256;
            int r = idx >> 2, c16 = (idx & 3) * 16;
            uint4 u = *(const uint4*)&sptr[(size_t)r * NN + c16];
            const int8_t* cb = (const int8_t*)&u;
            int mr = srm[r];
            float li = srli[r];
            #pragma unroll
            for (int z = 0; z < 16; z += 2) {
                float p0 = lut[mr - (int)cb[z]] * li;
                float p1 = lut[mr - (int)cb[z + 1]] * li;
                __nv_bfloat162 pr;
                pr.x = __float2bfloat16(rintf(fminf(p0 * inva2, 127.f)));
                pr.y = __float2bfloat16(rintf(fminf(p1 * inva2, 127.f)));
                *(__nv_bfloat162*)&sP[r][c16 + z] = pr;
            }
        }
        // V tile transposed: sV[d][k]
        const bf16* vptr = g_v + ((size_t)bh * NN + ct2 * 64) * DD;
        #pragma unroll
        for (int t = 0; t < 2; t++) {
            int idx = tid + t * 256;
            int kk = idx >> 3, c8 = (idx & 7) * 8;
            uint4 u = *(const uint4*)&vptr[(size_t)kk * DD + c8];
            const bf16* pv = (const bf16*)&u;
            #pragma unroll
            for (int z = 0; z < 8; z++) sV[c8 + z][kk] = pv[z];
        }
        __syncthreads();

        #pragma unroll
        for (int ks = 0; ks < 4; ks++) {
            uint32_t af[4][4];
            #pragma unroll
            for (int i = 0; i < 4; i++) {
                int rb = wm * 64 + i * 16;
                af[i][0] = *(const uint32_t*)&sP[rb + gr][ks * 16 + gc];
                af[i][1] = *(const uint32_t*)&sP[rb + gr + 8][ks * 16 + gc];
                af[i][2] = *(const uint32_t*)&sP[rb + gr][ks * 16 + gc + 8];
                af[i][3] = *(const uint32_t*)&sP[rb + gr + 8][ks * 16 + gc + 8];
            }
            #pragma unroll
            for (int j = 0; j < 2; j++) {
                int nb = wn * 16 + j * 8;
                uint32_t b0 = *(const uint32_t*)&sV[nb + gr][ks * 16 + gc];
                uint32_t b1 = *(const uint32_t*)&sV[nb + gr][ks * 16 + gc + 8];
                #pragma unroll
                for (int i = 0; i < 4; i++) mma16816(acco[i][j], af[i], b0, b1);
            }
        }
        __syncthreads();
    }

    // epilogue: scale by a_attn2*a_v, quantize with a_proj_a, store [B,N,C] levels
    int b = bh / HH, h = bh % HH;
    float so = a_attn2[0] * a_v[0];
    float invpa = 1.f / a_proj_a[0];
    #pragma unroll
    for (int i = 0; i < 4; i++)
        #pragma unroll
        for (int j = 0; j < 2; j++)
            #pragma unroll
            for (int c = 0; c < 4; c++) {
                int n = rt0 + wm * 64 + i * 16 + gr + ((c >> 1) * 8);
                int d = wn * 16 + j * 8 + gc + (c & 1);
                float lvl = qlvl(acco[i][j][c] * so, invpa);
                g_o[((size_t)(b * NN + n)) * CC + h * 64 + d] =
                    __float2bfloat16(lvl);
            }
}

// ---------------- kernel 4: projection GEMM (M=4096, N=384, K=384) + bias ----------------
__global__ __launch_bounds__(256) void k_proj(
        float* __restrict__ out, const float* __restrict__ bproj,
        const float* __restrict__ a_proj_a, const float* __restrict__ a_proj_w) {
    __shared__ bf16 sA[128][48];
    __shared__ bf16 sB[128][48];

    int tid = threadIdx.x, lane = tid & 31, wid = tid >> 5;
    int wm = wid & 1, wn = wid >> 1;
    int gr = lane >> 2, gc = (lane & 3) * 2;
    int m0 = blockIdx.x * 128, n0 = blockIdx.y * 128;

    float acc[4][4][4];
    #pragma unroll
    for (int i = 0; i < 4; i++)
        #pragma unroll
        for (int j = 0; j < 4; j++)
            #pragma unroll
            for (int c = 0; c < 4; c++) acc[i][j][c] = 0.f;

    for (int kt = 0; kt < 12; kt++) {
        #pragma unroll
        for (int t = 0; t < 2; t++) {
            int idx = tid + t * 256;
            int r = idx >> 2, c8 = (idx & 3) * 8;
            *(uint4*)&sA[r][c8] =
                *(const uint4*)&g_o[(size_t)(m0 + r) * CC + kt * 32 + c8];
        }
        #pragma unroll
        for (int t = 0; t < 2; t++) {
            int idx = tid + t * 256;
            int r = idx >> 2, c8 = (idx & 3) * 8;
            *(uint4*)&sB[r][c8] =
                *(const uint4*)&g_wproj[(size_t)(n0 + r) * CC + kt * 32 + c8];
        }
        __syncthreads();
        #pragma unroll
        for (int ks = 0; ks < 2; ks++) {
            uint32_t af[4][4], bfr[4][2];
            #pragma unroll
            for (int i = 0; i < 4; i++) {
                int rb = wm * 64 + i * 16;
                af[i][0] = *(const uint32_t*)&sA[rb + gr][ks * 16 + gc];
                af[i][1] = *(const uint32_t*)&sA[rb + gr + 8][ks * 16 + gc];
                af[i][2] = *(const uint32_t*)&sA[rb + gr][ks * 16 + gc + 8];
                af[i][3] = *(const uint32_t*)&sA[rb + gr + 8][ks * 16 + gc + 8];
            }
            #pragma unroll
            for (int j = 0; j < 4; j++) {
                int nb = wn * 32 + j * 8;
                bfr[j][0] = *(const uint32_t*)&sB[nb + gr][ks * 16 + gc];
                bfr[j][1] = *(const uint32_t*)&sB[nb + gr][ks * 16 + gc + 8];
            }
            #pragma unroll
            for (int i = 0; i < 4; i++)
                #pragma unroll
                for (int j = 0; j < 4; j++)
                    mma16816(acc[i][j], af[i], bfr[j][0], bfr[j][1]);
        }
        __syncthreads();
    }

    float sc = a_proj_a[0] * a_proj_w[0];
    #pragma unroll
    for (int i = 0; i < 4; i++)
        #pragma unroll
        for (int j = 0; j < 4; j++)
            #pragma unroll
            for (int c = 0; c < 4; c++) {
                int row = m0 + wm * 64 + i * 16 + gr + ((c >> 1) * 8);
                int col = n0 + wn * 32 + j * 8 + gc + (c & 1);
                out[(size_t)row * CC + col] = acc[i][j][c] * sc + bproj[col];
            }
}

// ---------------- launch ----------------
extern "C" void kernel_launch(void* const* d_in, const int* in_sizes, int n_in,
                              void* d_out, int out_size) {
    const float* x        = (const float*)d_in[0];
    const float* wqkv     = (const float*)d_in[1];
    const float* wproj    = (const float*)d_in[2];
    const float* bproj    = (const float*)d_in[3];
    const float* a_qkv_w  = (const float*)d_in[4];
    const float* a_qkv_a  = (const float*)d_in[5];
    const float* a_proj_w = (const float*)d_in[6];
    const float* a_proj_a = (const float*)d_in[7];
    const float* a_q      = (const float*)d_in[8];
    const float* a_k      = (const float*)d_in[9];
    const float* a_v      = (const float*)d_in[10];
    const float* a_attn   = (const float*)d_in[11];
    const float* a_attn2  = (const float*)d_in[12];
    float* out = (float*)d_out;

    k_quant_w<<<(TCC * CC + 255) / 256, 256>>>(wqkv, wproj, a_qkv_w, a_proj_w);
    k_qkv<<<dim3(32, 9), 256>>>(x, a_qkv_a, a_qkv_w, a_q, a_k, a_v);
    k_attn<<<dim3(16, 12), 256>>>(a_q, a_k, a_attn, a_attn2, a_v, a_proj_a);
    k_proj<<<dim3(32, 3), 256>>>(out, bproj, a_proj_a, a_proj_w);
}

// round 3
// speedup vs baseline: 1.6127x; 1.6127x over previous
#include <cuda_runtime.h>
#include <cuda_bf16.h>
#include <cstdint>
#include <math.h>

#define BB 2
#define NN 2048
#define CC 384
#define HH 6
#define DD 64
#define TCC 1152   // 3*C
#define MM 4096    // B*N

typedef __nv_bfloat16 bf16;

// ---------------- device scratch ----------------
__device__ bf16 g_wqkv[TCC * CC];
__device__ bf16 g_wproj[CC * CC];
__device__ bf16 g_q[BB * HH * NN * DD];
__device__ bf16 g_k[BB * HH * NN * DD];
__device__ bf16 g_v[BB * HH * NN * DD];
__device__ bf16 g_o[(size_t)MM * CC];

// ---------------- helpers ----------------
__device__ __forceinline__ float qlvl(float x, float inv_alpha) {
    float s = x * inv_alpha;
    s = fminf(fmaxf(s, -128.f), 127.f);
    return rintf(s);
}

__device__ __forceinline__ void mma16816(float* c, const uint32_t* a,
                                         uint32_t b0, uint32_t b1) {
    asm volatile(
        "mma.sync.aligned.m16n8k16.row.col.f32.bf16.bf16.f32 "
        "{%0,%1,%2,%3}, {%4,%5,%6,%7}, {%8,%9}, {%0,%1,%2,%3};\n"
        : "+f"(c[0]), "+f"(c[1]), "+f"(c[2]), "+f"(c[3])
        : "r"(a[0]), "r"(a[1]), "r"(a[2]), "r"(a[3]), "r"(b0), "r"(b1));
}

__device__ __forceinline__ uint32_t sptr(const void* p) {
    return (uint32_t)__cvta_generic_to_shared(p);
}

__device__ __forceinline__ void ldsm4(uint32_t* r, uint32_t addr) {
    asm volatile("ldmatrix.sync.aligned.m8n8.x4.shared.b16 {%0,%1,%2,%3},[%4];\n"
                 : "=r"(r[0]), "=r"(r[1]), "=r"(r[2]), "=r"(r[3]) : "r"(addr));
}

__device__ __forceinline__ void ldsm4t(uint32_t* r, uint32_t addr) {
    asm volatile("ldmatrix.sync.aligned.m8n8.x4.trans.shared.b16 {%0,%1,%2,%3},[%4];\n"
                 : "=r"(r[0]), "=r"(r[1]), "=r"(r[2]), "=r"(r[3]) : "r"(addr));
}

// ---------------- kernel 1: quantize weights ----------------
__global__ void k_quant_w(const float* __restrict__ wqkv,
                          const float* __restrict__ wproj,
                          const float* __restrict__ a_qkv_w,
                          const float* __restrict__ a_proj_w) {
    float i1 = 1.f / a_qkv_w[0];
    float i2 = 1.f / a_proj_w[0];
    int i = blockIdx.x * 256 + threadIdx.x;
    if (i < TCC * CC) g_wqkv[i]  = __float2bfloat16(qlvl(wqkv[i], i1));
    if (i < CC * CC)  g_wproj[i] = __float2bfloat16(qlvl(wproj[i], i2));
}

// ---------------- kernel 2: QKV GEMM 4096x1152x384, CTA 64x128 ----------------
__global__ __launch_bounds__(256) void k_qkv(
        const float* __restrict__ x,
        const float* __restrict__ a_qkv_a, const float* __restrict__ a_qkv_w,
        const float* __restrict__ a_q, const float* __restrict__ a_k,
        const float* __restrict__ a_v) {
    __shared__ bf16 sA[64][40];
    __shared__ bf16 sB[128][40];

    int tid = threadIdx.x, lane = tid & 31, wid = tid >> 5;
    int wm = wid & 3, wn = wid >> 2;
    int gr = lane >> 2, gc = (lane & 3) * 2;
    int lr_a = lane & 15, lc_a = (lane >> 4) << 3;
    int lr_b = ((lane >> 4) << 3) + (lane & 7), lc_b = ((lane >> 3) & 1) << 3;
    int m0 = blockIdx.x * 64, n0 = blockIdx.y * 128;
    float invaa = 1.f / a_qkv_a[0];

    float acc[8][4];
    #pragma unroll
    for (int i = 0; i < 8; i++)
        #pragma unroll
        for (int c = 0; c < 4; c++) acc[i][c] = 0.f;

    for (int kt = 0; kt < 12; kt++) {
        #pragma unroll
        for (int t = 0; t < 2; t++) {
            int idx = tid + t * 256;
            int r = idx >> 3, c4 = (idx & 7) * 4;
            float4 v = *(const float4*)&x[(size_t)(m0 + r) * CC + kt * 32 + c4];
            __nv_bfloat162 p0, p1;
            p0.x = __float2bfloat16(qlvl(v.x, invaa));
            p0.y = __float2bfloat16(qlvl(v.y, invaa));
            p1.x = __float2bfloat16(qlvl(v.z, invaa));
            p1.y = __float2bfloat16(qlvl(v.w, invaa));
            *(__nv_bfloat162*)&sA[r][c4] = p0;
            *(__nv_bfloat162*)&sA[r][c4 + 2] = p1;
        }
        #pragma unroll
        for (int t = 0; t < 2; t++) {
            int idx = tid + t * 256;
            int r = idx >> 2, c8 = (idx & 3) * 8;
            *(uint4*)&sB[r][c8] =
                *(const uint4*)&g_wqkv[(size_t)(n0 + r) * CC + kt * 32 + c8];
        }
        __syncthreads();
        #pragma unroll
        for (int kc = 0; kc < 2; kc++) {
            uint32_t af[4];
            ldsm4(af, sptr(&sA[wm * 16 + lr_a][kc * 16 + lc_a]));
            #pragma unroll
            for (int np = 0; np < 4; np++) {
                uint32_t bfr[4];
                ldsm4(bfr, sptr(&sB[wn * 64 + np * 16 + lr_b][kc * 16 + lc_b]));
                mma16816(acc[2 * np], af, bfr[0], bfr[1]);
                mma16816(acc[2 * np + 1], af, bfr[2], bfr[3]);
            }
        }
        __syncthreads();
    }

    int which = (n0 >= 768) ? 2 : (n0 >= 384 ? 1 : 0);
    const float* a3 = (which == 0) ? a_q : (which == 1 ? a_k : a_v);
    float inv3 = 1.f / a3[0];
    float sAB = a_qkv_a[0] * a_qkv_w[0];
    bf16* dst = (which == 0) ? g_q : (which == 1 ? g_k : g_v);
    int ncol0 = n0 - which * CC;
    #pragma unroll
    for (int nc = 0; nc < 8; nc++)
        #pragma unroll
        for (int h2 = 0; h2 < 2; h2++) {
            int row = m0 + wm * 16 + gr + h2 * 8;
            int col = ncol0 + wn * 64 + nc * 8 + gc;
            int b = row >> 11, n = row & 2047;
            int h = col >> 6, d = col & 63;
            __nv_bfloat162 pr;
            pr.x = __float2bfloat16(qlvl(acc[nc][2 * h2] * sAB, inv3));
            pr.y = __float2bfloat16(qlvl(acc[nc][2 * h2 + 1] * sAB, inv3));
            *(__nv_bfloat162*)&dst[(((size_t)(b * HH + h)) * NN + n) * DD + d] = pr;
        }
}

// ---------------- kernel 3: fused attention, CTA = 64 Q rows, no scratch ----------------
__global__ __launch_bounds__(128) void k_attn(
        const float* __restrict__ a_q, const float* __restrict__ a_k,
        const float* __restrict__ a_attn, const float* __restrict__ a_attn2,
        const float* __restrict__ a_v, const float* __restrict__ a_proj_a) {
    __shared__ bf16 sK[64][80];
    __shared__ bf16 sV[64][80];
    __shared__ float lut[260];

    int tid = threadIdx.x, lane = tid & 31, wid = tid >> 5;
    int gr = lane >> 2, gc = (lane & 3) * 2;
    int lr_a = lane & 15, lc_a = (lane >> 4) << 3;
    int lr_b = ((lane >> 4) << 3) + (lane & 7), lc_b = ((lane >> 3) & 1) << 3;
    int bh = blockIdx.y;
    int rt0 = blockIdx.x * 64;
    int wr = wid * 16;

    float aat = a_attn[0];
    float fsc = a_q[0] * a_k[0] * 0.125f / aat;

    for (int i = tid; i < 260; i += 128) lut[i] = expf(-(float)i * aat);

    // stage Q into sK, build resident A fragments
    const bf16* qptr = g_q + ((size_t)bh * NN + rt0) * DD;
    #pragma unroll
    for (int t = 0; t < 4; t++) {
        int idx = tid + t * 128;
        int r = idx >> 3, c8 = (idx & 7) * 8;
        *(uint4*)&sK[r][c8] = *(const uint4*)&qptr[(size_t)r * DD + c8];
    }
    __syncthreads();
    uint32_t qf[4][4];
    #pragma unroll
    for (int kc = 0; kc < 4; kc++)
        ldsm4(qf[kc], sptr(&sK[wr + lr_a][kc * 16 + lc_a]));
    __syncthreads();

    int   tm[2] = {-300, -300};
    float tl[2] = {0.f, 0.f};

    // ---------- pass 1: stats only ----------
    for (int ct = 0; ct < 32; ct++) {
        const bf16* kp = g_k + ((size_t)bh * NN + ct * 64) * DD;
        #pragma unroll
        for (int t = 0; t < 4; t++) {
            int idx = tid + t * 128;
            int r = idx >> 3, c8 = (idx & 7) * 8;
            *(uint4*)&sK[r][c8] = *(const uint4*)&kp[(size_t)r * DD + c8];
        }
        __syncthreads();

        float sacc[8][4];
        #pragma unroll
        for (int i = 0; i < 8; i++)
            #pragma unroll
            for (int c = 0; c < 4; c++) sacc[i][c] = 0.f;
        #pragma unroll
        for (int ks = 0; ks < 4; ks++)
            #pragma unroll
            for (int np = 0; np < 4; np++) {
                uint32_t bfr[4];
                ldsm4(bfr, sptr(&sK[np * 16 + lr_b][ks * 16 + lc_b]));
                mma16816(sacc[2 * np], qf[ks], bfr[0], bfr[1]);
                mma16816(sacc[2 * np + 1], qf[ks], bfr[2], bfr[3]);
            }

        #pragma unroll
        for (int nc = 0; nc < 8; nc++)
            #pragma unroll
            for (int h2 = 0; h2 < 2; h2++) {
                int l0 = __float2int_rn(fminf(fmaxf(sacc[nc][2 * h2] * fsc, -128.f), 127.f));
                int l1 = __float2int_rn(fminf(fmaxf(sacc[nc][2 * h2 + 1] * fsc, -128.f), 127.f));
                int mx = (l0 > l1) ? l0 : l1;
                if (mx > tm[h2]) {
                    tl[h2] = tl[h2] * lut[min(mx - tm[h2], 259)];
                    tm[h2] = mx;
                }
                tl[h2] += lut[tm[h2] - l0] + lut[tm[h2] - l1];
            }
        __syncthreads();
    }

    // reduce stats across the 4 lanes of each row quartet
    float tli[2];
    #pragma unroll
    for (int h2 = 0; h2 < 2; h2++) {
        int m = tm[h2];
        float l = tl[h2];
        #pragma unroll
        for (int off = 1; off <= 2; off <<= 1) {
            int m2 = __shfl_xor_sync(0xffffffff, m, off);
            float l2 = __shfl_xor_sync(0xffffffff, l, off);
            if (m2 > m) { float t = l; l = l2; l2 = t; int t2 = m; m = m2; m2 = t2; }
            l += l2 * lut[min(m - m2, 259)];
        }
        tm[h2] = m;
        tli[h2] = 1.f / l;
    }

    // ---------- pass 2: recompute S, fuse P in registers, P*V ----------
    float inva2 = 1.f / a_attn2[0];
    float liq0 = tli[0] * inva2, liq1 = tli[1] * inva2;
    float oacc[8][4];
    #pragma unroll
    for (int i = 0; i < 8; i++)
        #pragma unroll
        for (int c = 0; c < 4; c++) oacc[i][c] = 0.f;

    for (int ct = 0; ct < 32; ct++) {
        const bf16* kp = g_k + ((size_t)bh * NN + ct * 64) * DD;
        const bf16* vp = g_v + ((size_t)bh * NN + ct * 64) * DD;
        #pragma unroll
        for (int t = 0; t < 4; t++) {
            int idx = tid + t * 128;
            int r = idx >> 3, c8 = (idx & 7) * 8;
            *(uint4*)&sK[r][c8] = *(const uint4*)&kp[(size_t)r * DD + c8];
            *(uint4*)&sV[r][c8] = *(const uint4*)&vp[(size_t)r * DD + c8];
        }
        __syncthreads();

        float sacc[8][4];
        #pragma unroll
        for (int i = 0; i < 8; i++)
            #pragma unroll
            for (int c = 0; c < 4; c++) sacc[i][c] = 0.f;
        #pragma unroll
        for (int ks = 0; ks < 4; ks++)
            #pragma unroll
            for (int np = 0; np < 4; np++) {
                uint32_t bfr[4];
                ldsm4(bfr, sptr(&sK[np * 16 + lr_b][ks * 16 + lc_b]));
                mma16816(sacc[2 * np], qf[ks], bfr[0], bfr[1]);
                mma16816(sacc[2 * np + 1], qf[ks], bfr[2], bfr[3]);
            }

        // S fragments (f32) -> P level fragments (bf16 A-layout), in registers
        uint32_t pf[4][4];
        #pragma unroll
        for (int kc = 0; kc < 4; kc++) {
            int nc = 2 * kc, ncb = 2 * kc + 1;
            #pragma unroll
            for (int slot = 0; slot < 4; slot++) {
                int src = (slot & 2) ? ncb : nc;       // slots 2,3 -> upper 8 cols
                int h2 = slot & 1;                      // slots 1,3 -> rows gr+8
                float liq = h2 ? liq1 : liq0;
                int m = tm[h2];
                float s0 = (h2 ? sacc[src][2] : sacc[src][0]);
                float s1 = (h2 ? sacc[src][3] : sacc[src][1]);
                int l0 = __float2int_rn(fminf(fmaxf(s0 * fsc, -128.f), 127.f));
                int l1 = __float2int_rn(fminf(fmaxf(s1 * fsc, -128.f), 127.f));
                float p0 = rintf(fminf(lut[m - l0] * liq, 127.f));
                float p1 = rintf(fminf(lut[m - l1] * liq, 127.f));
                __nv_bfloat162 pr;
                pr.x = __float2bfloat16(p0);
                pr.y = __float2bfloat16(p1);
                pf[kc][slot] = *(uint32_t*)&pr;
            }
        }

        // P (16x64) x V (64x64): B fragments via ldmatrix.trans
        #pragma unroll
        for (int ks = 0; ks < 4; ks++)
            #pragma unroll
            for (int np = 0; np < 4; np++) {
                uint32_t bfr[4];
                ldsm4t(bfr, sptr(&sV[ks * 16 + lr_a][np * 16 + lc_a]));
                mma16816(oacc[2 * np], pf[ks], bfr[0], bfr[1]);
                mma16816(oacc[2 * np + 1], pf[ks], bfr[2], bfr[3]);
            }
        __syncthreads();
    }

    // epilogue: scale by a_attn2*a_v, quantize with a_proj_a, store levels
    int b = bh / HH, h = bh % HH;
    float so = a_attn2[0] * a_v[0];
    float invpa = 1.f / a_proj_a[0];
    #pragma unroll
    for (int nc = 0; nc < 8; nc++)
        #pragma unroll
        for (int h2 = 0; h2 < 2; h2++) {
            int n = rt0 + wr + gr + h2 * 8;
            int d = nc * 8 + gc;
            __nv_bfloat162 pr;
            pr.x = __float2bfloat16(qlvl(oacc[nc][2 * h2] * so, invpa));
            pr.y = __float2bfloat16(qlvl(oacc[nc][2 * h2 + 1] * so, invpa));
            *(__nv_bfloat162*)&g_o[((size_t)(b * NN + n)) * CC + h * 64 + d] = pr;
        }
}

// ---------------- kernel 4: projection GEMM 4096x384x384 + bias, CTA 64x128 ----------------
__global__ __launch_bounds__(256) void k_proj(
        float* __restrict__ out, const float* __restrict__ bproj,
        const float* __restrict__ a_proj_a, const float* __restrict__ a_proj_w) {
    __shared__ bf16 sA[64][40];
    __shared__ bf16 sB[128][40];

    int tid = threadIdx.x, lane = tid & 31, wid = tid >> 5;
    int wm = wid & 3, wn = wid >> 2;
    int gr = lane >> 2, gc = (lane & 3) * 2;
    int lr_a = lane & 15, lc_a = (lane >> 4) << 3;
    int lr_b = ((lane >> 4) << 3) + (lane & 7), lc_b = ((lane >> 3) & 1) << 3;
    int m0 = blockIdx.x * 64, n0 = blockIdx.y * 128;

    float acc[8][4];
    #pragma unroll
    for (int i = 0; i < 8; i++)
        #pragma unroll
        for (int c = 0; c < 4; c++) acc[i][c] = 0.f;

    for (int kt = 0; kt < 12; kt++) {
        {
            int idx = tid;
            int r = idx >> 2, c8 = (idx & 3) * 8;
            *(uint4*)&sA[r][c8] =
                *(const uint4*)&g_o[(size_t)(m0 + r) * CC + kt * 32 + c8];
        }
        #pragma unroll
        for (int t = 0; t < 2; t++) {
            int idx = tid + t * 256;
            int r = idx >> 2, c8 = (idx & 3) * 8;
            *(uint4*)&sB[r][c8] =
                *(const uint4*)&g_wproj[(size_t)(n0 + r) * CC + kt * 32 + c8];
        }
        __syncthreads();
        #pragma unroll
        for (int kc = 0; kc < 2; kc++) {
            uint32_t af[4];
            ldsm4(af, sptr(&sA[wm * 16 + lr_a][kc * 16 + lc_a]));
            #pragma unroll
            for (int np = 0; np < 4; np++) {
                uint32_t bfr[4];
                ldsm4(bfr, sptr(&sB[wn * 64 + np * 16 + lr_b][kc * 16 + lc_b]));
                mma16816(acc[2 * np], af, bfr[0], bfr[1]);
                mma16816(acc[2 * np + 1], af, bfr[2], bfr[3]);
            }
        }
        __syncthreads();
    }

    float sc = a_proj_a[0] * a_proj_w[0];
    #pragma unroll
    for (int nc = 0; nc < 8; nc++)
        #pragma unroll
        for (int h2 = 0; h2 < 2; h2++) {
            int row = m0 + wm * 16 + gr + h2 * 8;
            int col = n0 + wn * 64 + nc * 8 + gc;
            float2 r2;
            r2.x = acc[nc][2 * h2] * sc + bproj[col];
            r2.y = acc[nc][2 * h2 + 1] * sc + bproj[col + 1];
            *(float2*)&out[(size_t)row * CC + col] = r2;
        }
}

// ---------------- launch ----------------
extern "C" void kernel_launch(void* const* d_in, const int* in_sizes, int n_in,
                              void* d_out, int out_size) {
    const float* x        = (const float*)d_in[0];
    const float* wqkv     = (const float*)d_in[1];
    const float* wproj    = (const float*)d_in[2];
    const float* bproj    = (const float*)d_in[3];
    const float* a_qkv_w  = (const float*)d_in[4];
    const float* a_qkv_a  = (const float*)d_in[5];
    const float* a_proj_w = (const float*)d_in[6];
    const float* a_proj_a = (const float*)d_in[7];
    const float* a_q      = (const float*)d_in[8];
    const float* a_k      = (const float*)d_in[9];
    const float* a_v      = (const float*)d_in[10];
    const float* a_attn   = (const float*)d_in[11];
    const float* a_attn2  = (const float*)d_in[12];
    float* out = (float*)d_out;

    k_quant_w<<<(TCC * CC + 255) / 256, 256>>>(wqkv, wproj, a_qkv_w, a_proj_w);
    k_qkv<<<dim3(64, 9), 256>>>(x, a_qkv_a, a_qkv_w, a_q, a_k, a_v);
    k_attn<<<dim3(32, 12), 128>>>(a_q, a_k, a_attn, a_attn2, a_v, a_proj_a);
    k_proj<<<dim3(64, 3), 256>>>(out, bproj, a_proj_a, a_proj_w);
}

// round 7
// speedup vs baseline: 2.2459x; 1.3926x over previous
#include <cuda_runtime.h>
#include <cuda_bf16.h>
#include <cstdint>
#include <math.h>

#define BB 2
#define NN 2048
#define CC 384
#define HH 6
#define DD 64
#define TCC 1152   // 3*C
#define MM 4096    // B*N

typedef __nv_bfloat16 bf16;

// ---------------- device scratch ----------------
__device__ bf16 g_wqkv[TCC * CC];
__device__ bf16 g_wproj[CC * CC];
__device__ bf16 g_xq[(size_t)MM * CC];
__device__ bf16 g_q[BB * HH * NN * DD];
__device__ bf16 g_k[BB * HH * NN * DD];
__device__ bf16 g_v[BB * HH * NN * DD];
__device__ bf16 g_o[(size_t)MM * CC];

// ---------------- helpers ----------------
__device__ __forceinline__ float qlvl(float x, float inv_alpha) {
    float s = x * inv_alpha;
    s = fminf(fmaxf(s, -128.f), 127.f);
    return rintf(s);
}

__device__ __forceinline__ void mma16816(float* c, const uint32_t* a,
                                         uint32_t b0, uint32_t b1) {
    asm volatile(
        "mma.sync.aligned.m16n8k16.row.col.f32.bf16.bf16.f32 "
        "{%0,%1,%2,%3}, {%4,%5,%6,%7}, {%8,%9}, {%0,%1,%2,%3};\n"
        : "+f"(c[0]), "+f"(c[1]), "+f"(c[2]), "+f"(c[3])
        : "r"(a[0]), "r"(a[1]), "r"(a[2]), "r"(a[3]), "r"(b0), "r"(b1));
}

__device__ __forceinline__ uint32_t sptr(const void* p) {
    return (uint32_t)__cvta_generic_to_shared(p);
}

__device__ __forceinline__ void ldsm4(uint32_t* r, uint32_t addr) {
    asm volatile("ldmatrix.sync.aligned.m8n8.x4.shared.b16 {%0,%1,%2,%3},[%4];\n"
                 : "=r"(r[0]), "=r"(r[1]), "=r"(r[2]), "=r"(r[3]) : "r"(addr));
}

__device__ __forceinline__ void ldsm4t(uint32_t* r, uint32_t addr) {
    asm volatile("ldmatrix.sync.aligned.m8n8.x4.trans.shared.b16 {%0,%1,%2,%3},[%4];\n"
                 : "=r"(r[0]), "=r"(r[1]), "=r"(r[2]), "=r"(r[3]) : "r"(addr));
}

__device__ __forceinline__ void cpa16(uint32_t d, const void* s) {
    asm volatile("cp.async.cg.shared.global [%0], [%1], 16;\n" :: "r"(d), "l"(s));
}
__device__ __forceinline__ void cpcommit() {
    asm volatile("cp.async.commit_group;\n");
}
template <int N>
__device__ __forceinline__ void cpwait() {
    asm volatile("cp.async.wait_group %0;\n" :: "n"(N));
}

// ---------------- kernel 1: quantize weights + x to bf16 levels ----------------
__global__ __launch_bounds__(256) void k_quant(
        const float* __restrict__ x,
        const float* __restrict__ wqkv, const float* __restrict__ wproj,
        const float* __restrict__ a_qkv_w, const float* __restrict__ a_proj_w,
        const float* __restrict__ a_qkv_a) {
    float i1 = 1.f / a_qkv_w[0];
    float i2 = 1.f / a_proj_w[0];
    float i3 = 1.f / a_qkv_a[0];
    int i4 = (blockIdx.x * 256 + threadIdx.x) * 4;

    if (i4 < MM * CC) {
        float4 v = *(const float4*)&x[i4];
        __nv_bfloat162 p0, p1;
        p0.x = __float2bfloat16(qlvl(v.x, i3));
        p0.y = __float2bfloat16(qlvl(v.y, i3));
        p1.x = __float2bfloat16(qlvl(v.z, i3));
        p1.y = __float2bfloat16(qlvl(v.w, i3));
        *(__nv_bfloat162*)&g_xq[i4] = p0;
        *(__nv_bfloat162*)&g_xq[i4 + 2] = p1;
    }
    if (i4 < TCC * CC) {
        float4 v = *(const float4*)&wqkv[i4];
        __nv_bfloat162 p0, p1;
        p0.x = __float2bfloat16(qlvl(v.x, i1));
        p0.y = __float2bfloat16(qlvl(v.y, i1));
        p1.x = __float2bfloat16(qlvl(v.z, i1));
        p1.y = __float2bfloat16(qlvl(v.w, i1));
        *(__nv_bfloat162*)&g_wqkv[i4] = p0;
        *(__nv_bfloat162*)&g_wqkv[i4 + 2] = p1;
    }
    if (i4 < CC * CC) {
        float4 v = *(const float4*)&wproj[i4];
        __nv_bfloat162 p0, p1;
        p0.x = __float2bfloat16(qlvl(v.x, i2));
        p0.y = __float2bfloat16(qlvl(v.y, i2));
        p1.x = __float2bfloat16(qlvl(v.z, i2));
        p1.y = __float2bfloat16(qlvl(v.w, i2));
        *(__nv_bfloat162*)&g_wproj[i4] = p0;
        *(__nv_bfloat162*)&g_wproj[i4 + 2] = p1;
    }
}

// ---------------- kernel 2: QKV GEMM 4096x1152x384, CTA 64x128, cp.async pipelined ----------------
__global__ __launch_bounds__(256) void k_qkv(
        const float* __restrict__ a_qkv_a, const float* __restrict__ a_qkv_w,
        const float* __restrict__ a_q, const float* __restrict__ a_k,
        const float* __restrict__ a_v) {
    __shared__ bf16 sA[2][64][40];
    __shared__ bf16 sB[2][128][40];

    int tid = threadIdx.x, lane = tid & 31, wid = tid >> 5;
    int wm = wid & 3, wn = wid >> 2;
    int gr = lane >> 2, gc = (lane & 3) * 2;
    int lr_a = lane & 15, lc_a = (lane >> 4) << 3;
    int lr_b = ((lane >> 4) << 3) + (lane & 7), lc_b = ((lane >> 3) & 1) << 3;
    int m0 = blockIdx.x * 64, n0 = blockIdx.y * 128;

    int ra = tid >> 2, ca = (tid & 3) * 8;
    int rb = tid >> 2, cb = (tid & 3) * 8;

    float acc[8][4];
    #pragma unroll
    for (int i = 0; i < 8; i++)
        #pragma unroll
        for (int c = 0; c < 4; c++) acc[i][c] = 0.f;

    // prologue prefetch kt=0
    {
        cpa16(sptr(&sA[0][ra][ca]), &g_xq[(size_t)(m0 + ra) * CC + ca]);
        cpa16(sptr(&sB[0][rb][cb]), &g_wqkv[(size_t)(n0 + rb) * CC + cb]);
        cpa16(sptr(&sB[0][rb + 64][cb]), &g_wqkv[(size_t)(n0 + rb + 64) * CC + cb]);
        cpcommit();
    }

    for (int kt = 0; kt < 12; kt++) {
        int buf = kt & 1;
        if (kt < 11) {
            int nb2 = buf ^ 1, kc0 = (kt + 1) * 32;
            cpa16(sptr(&sA[nb2][ra][ca]), &g_xq[(size_t)(m0 + ra) * CC + kc0 + ca]);
            cpa16(sptr(&sB[nb2][rb][cb]), &g_wqkv[(size_t)(n0 + rb) * CC + kc0 + cb]);
            cpa16(sptr(&sB[nb2][rb + 64][cb]), &g_wqkv[(size_t)(n0 + rb + 64) * CC + kc0 + cb]);
            cpcommit();
            cpwait<1>();
        } else {
            cpwait<0>();
        }
        __syncthreads();
        #pragma unroll
        for (int kc = 0; kc < 2; kc++) {
            uint32_t af[4];
            ldsm4(af, sptr(&sA[buf][wm * 16 + lr_a][kc * 16 + lc_a]));
            #pragma unroll
            for (int np = 0; np < 4; np++) {
                uint32_t bfr[4];
                ldsm4(bfr, sptr(&sB[buf][wn * 64 + np * 16 + lr_b][kc * 16 + lc_b]));
                mma16816(acc[2 * np], af, bfr[0], bfr[1]);
                mma16816(acc[2 * np + 1], af, bfr[2], bfr[3]);
            }
        }
        __syncthreads();
    }

    int which = (n0 >= 768) ? 2 : (n0 >= 384 ? 1 : 0);
    const float* a3 = (which == 0) ? a_q : (which == 1 ? a_k : a_v);
    float inv3 = 1.f / a3[0];
    float sAB = a_qkv_a[0] * a_qkv_w[0];
    bf16* dst = (which == 0) ? g_q : (which == 1 ? g_k : g_v);
    int ncol0 = n0 - which * CC;
    #pragma unroll
    for (int nc = 0; nc < 8; nc++)
        #pragma unroll
        for (int h2 = 0; h2 < 2; h2++) {
            int row = m0 + wm * 16 + gr + h2 * 8;
            int col = ncol0 + wn * 64 + nc * 8 + gc;
            int b = row >> 11, n = row & 2047;
            int h = col >> 6, d = col & 63;
            __nv_bfloat162 pr;
            pr.x = __float2bfloat16(qlvl(acc[nc][2 * h2] * sAB, inv3));
            pr.y = __float2bfloat16(qlvl(acc[nc][2 * h2 + 1] * sAB, inv3));
            *(__nv_bfloat162*)&dst[(((size_t)(b * HH + h)) * NN + n) * DD + d] = pr;
        }
}

// ---------------- kernel 3: fused attention, 64 Q rows/CTA, cp.async pipelined ----------------
__global__ __launch_bounds__(128) void k_attn(
        const float* __restrict__ a_q, const float* __restrict__ a_k,
        const float* __restrict__ a_attn, const float* __restrict__ a_attn2,
        const float* __restrict__ a_v, const float* __restrict__ a_proj_a) {
    __shared__ bf16 sK[2][64][72];
    __shared__ bf16 sV[2][64][72];
    __shared__ float lut[260];

    int tid = threadIdx.x, lane = tid & 31, wid = tid >> 5;
    int gr = lane >> 2, gc = (lane & 3) * 2;
    int lr_a = lane & 15, lc_a = (lane >> 4) << 3;
    int lr_b = ((lane >> 4) << 3) + (lane & 7), lc_b = ((lane >> 3) & 1) << 3;
    int bh = blockIdx.y;
    int rt0 = blockIdx.x * 64;
    int wr = wid * 16;

    float aat = a_attn[0];
    float fsc = a_q[0] * a_k[0] * 0.125f / aat;

    for (int i = tid; i < 260; i += 128) lut[i] = expf(-(float)i * aat);

    const bf16* kbase = g_k + (size_t)bh * NN * DD;
    const bf16* vbase = g_v + (size_t)bh * NN * DD;

    // stage Q into sK[0], build resident A fragments
    const bf16* qptr = g_q + ((size_t)bh * NN + rt0) * DD;
    #pragma unroll
    for (int t = 0; t < 4; t++) {
        int idx = tid + t * 128;
        int r = idx >> 3, c8 = (idx & 7) * 8;
        *(uint4*)&sK[0][r][c8] = *(const uint4*)&qptr[(size_t)r * DD + c8];
    }
    __syncthreads();
    uint32_t qf[4][4];
    #pragma unroll
    for (int kc = 0; kc < 4; kc++)
        ldsm4(qf[kc], sptr(&sK[0][wr + lr_a][kc * 16 + lc_a]));
    __syncthreads();

    int   tm[2] = {-300, -300};
    float tl[2] = {0.f, 0.f};

    // prefetch K tile 0
    #pragma unroll
    for (int t = 0; t < 4; t++) {
        int idx = tid + t * 128;
        int r = idx >> 3, c16 = (idx & 7) * 8;
        cpa16(sptr(&sK[0][r][c16]), &kbase[(size_t)r * DD + c16]);
    }
    cpcommit();

    // ---------- pass 1: stats only ----------
    for (int ct = 0; ct < 32; ct++) {
        int buf = ct & 1;
        if (ct < 31) {
            const bf16* kp = kbase + (size_t)(ct + 1) * 64 * DD;
            #pragma unroll
            for (int t = 0; t < 4; t++) {
                int idx = tid + t * 128;
                int r = idx >> 3, c16 = (idx & 7) * 8;
                cpa16(sptr(&sK[buf ^ 1][r][c16]), &kp[(size_t)r * DD + c16]);
            }
            cpcommit();
            cpwait<1>();
        } else {
            cpwait<0>();
        }
        __syncthreads();

        float sacc[8][4];
        #pragma unroll
        for (int i = 0; i < 8; i++)
            #pragma unroll
            for (int c = 0; c < 4; c++) sacc[i][c] = 0.f;
        #pragma unroll
        for (int ks = 0; ks < 4; ks++)
            #pragma unroll
            for (int np = 0; np < 4; np++) {
                uint32_t bfr[4];
                ldsm4(bfr, sptr(&sK[buf][np * 16 + lr_b][ks * 16 + lc_b]));
                mma16816(sacc[2 * np], qf[ks], bfr[0], bfr[1]);
                mma16816(sacc[2 * np + 1], qf[ks], bfr[2], bfr[3]);
            }

        #pragma unroll
        for (int nc = 0; nc < 8; nc++)
            #pragma unroll
            for (int h2 = 0; h2 < 2; h2++) {
                int l0 = __float2int_rn(fminf(fmaxf(sacc[nc][2 * h2] * fsc, -128.f), 127.f));
                int l1 = __float2int_rn(fminf(fmaxf(sacc[nc][2 * h2 + 1] * fsc, -128.f), 127.f));
                int mx = (l0 > l1) ? l0 : l1;
                if (mx > tm[h2]) {
                    tl[h2] = tl[h2] * lut[min(mx - tm[h2], 259)];
                    tm[h2] = mx;
                }
                tl[h2] += lut[tm[h2] - l0] + lut[tm[h2] - l1];
            }
        __syncthreads();
    }

    // prefetch K+V tile 0 for pass 2 (overlaps the stat reduction below)
    #pragma unroll
    for (int t = 0; t < 4; t++) {
        int idx = tid + t * 128;
        int r = idx >> 3, c16 = (idx & 7) * 8;
        cpa16(sptr(&sK[0][r][c16]), &kbase[(size_t)r * DD + c16]);
        cpa16(sptr(&sV[0][r][c16]), &vbase[(size_t)r * DD + c16]);
    }
    cpcommit();

    // reduce stats across the 4 lanes of each row quartet
    float tli[2];
    #pragma unroll
    for (int h2 = 0; h2 < 2; h2++) {
        int m = tm[h2];
        float l = tl[h2];
        #pragma unroll
        for (int off = 1; off <= 2; off <<= 1) {
            int m2 = __shfl_xor_sync(0xffffffff, m, off);
            float l2 = __shfl_xor_sync(0xffffffff, l, off);
            if (m2 > m) { float t = l; l = l2; l2 = t; int t2 = m; m = m2; m2 = t2; }
            l += l2 * lut[min(m - m2, 259)];
        }
        tm[h2] = m;
        tli[h2] = 1.f / l;
    }

    // ---------- pass 2: recompute S, fuse P in registers, P*V ----------
    float inva2 = 1.f / a_attn2[0];
    float liq0 = tli[0] * inva2, liq1 = tli[1] * inva2;
    float oacc[8][4];
    #pragma unroll
    for (int i = 0; i < 8; i++)
        #pragma unroll
        for (int c = 0; c < 4; c++) oacc[i][c] = 0.f;

    for (int ct = 0; ct < 32; ct++) {
        int buf = ct & 1;
        if (ct < 31) {
            const bf16* kp = kbase + (size_t)(ct + 1) * 64 * DD;
            const bf16* vp = vbase + (size_t)(ct + 1) * 64 * DD;
            #pragma unroll
            for (int t = 0; t < 4; t++) {
                int idx = tid + t * 128;
                int r = idx >> 3, c16 = (idx & 7) * 8;
                cpa16(sptr(&sK[buf ^ 1][r][c16]), &kp[(size_t)r * DD + c16]);
                cpa16(sptr(&sV[buf ^ 1][r][c16]), &vp[(size_t)r * DD + c16]);
            }
            cpcommit();
            cpwait<1>();
        } else {
            cpwait<0>();
        }
        __syncthreads();

        float sacc[8][4];
        #pragma unroll
        for (int i = 0; i < 8; i++)
            #pragma unroll
            for (int c = 0; c < 4; c++) sacc[i][c] = 0.f;
        #pragma unroll
        for (int ks = 0; ks < 4; ks++)
            #pragma unroll
            for (int np = 0; np < 4; np++) {
                uint32_t bfr[4];
                ldsm4(bfr, sptr(&sK[buf][np * 16 + lr_b][ks * 16 + lc_b]));
                mma16816(sacc[2 * np], qf[ks], bfr[0], bfr[1]);
                mma16816(sacc[2 * np + 1], qf[ks], bfr[2], bfr[3]);
            }

        // S fragments (f32) -> P level fragments (bf16 A-layout), in registers
        uint32_t pf[4][4];
        #pragma unroll
        for (int kc = 0; kc < 4; kc++) {
            int nc = 2 * kc, ncb = 2 * kc + 1;
            #pragma unroll
            for (int slot = 0; slot < 4; slot++) {
                int src = (slot & 2) ? ncb : nc;
                int h2 = slot & 1;
                float liq = h2 ? liq1 : liq0;
                int m = tm[h2];
                float s0 = (h2 ? sacc[src][2] : sacc[src][0]);
                float s1 = (h2 ? sacc[src][3] : sacc[src][1]);
                int l0 = __float2int_rn(fminf(fmaxf(s0 * fsc, -128.f), 127.f));
                int l1 = __float2int_rn(fminf(fmaxf(s1 * fsc, -128.f), 127.f));
                float p0 = rintf(fminf(lut[m - l0] * liq, 127.f));
                float p1 = rintf(fminf(lut[m - l1] * liq, 127.f));
                __nv_bfloat162 pr;
                pr.x = __float2bfloat16(p0);
                pr.y = __float2bfloat16(p1);
                pf[kc][slot] = *(uint32_t*)&pr;
            }
        }

        #pragma unroll
        for (int ks = 0; ks < 4; ks++)
            #pragma unroll
            for (int np = 0; np < 4; np++) {
                uint32_t bfr[4];
                ldsm4t(bfr, sptr(&sV[buf][ks * 16 + lr_a][np * 16 + lc_a]));
                mma16816(oacc[2 * np], pf[ks], bfr[0], bfr[1]);
                mma16816(oacc[2 * np + 1], pf[ks], bfr[2], bfr[3]);
            }
        __syncthreads();
    }

    // epilogue
    int b = bh / HH, h = bh % HH;
    float so = a_attn2[0] * a_v[0];
    float invpa = 1.f / a_proj_a[0];
    #pragma unroll
    for (int nc = 0; nc < 8; nc++)
        #pragma unroll
        for (int h2 = 0; h2 < 2; h2++) {
            int n = rt0 + wr + gr + h2 * 8;
            int d = nc * 8 + gc;
            __nv_bfloat162 pr;
            pr.x = __float2bfloat16(qlvl(oacc[nc][2 * h2] * so, invpa));
            pr.y = __float2bfloat16(qlvl(oacc[nc][2 * h2 + 1] * so, invpa));
            *(__nv_bfloat162*)&g_o[((size_t)(b * NN + n)) * CC + h * 64 + d] = pr;
        }
}

// ---------------- kernel 4: projection GEMM 4096x384x384 + bias, cp.async pipelined ----------------
__global__ __launch_bounds__(256) void k_proj(
        float* __restrict__ out, const float* __restrict__ bproj,
        const float* __restrict__ a_proj_a, const float* __restrict__ a_proj_w) {
    __shared__ bf16 sA[2][64][40];
    __shared__ bf16 sB[2][128][40];

    int tid = threadIdx.x, lane = tid & 31, wid = tid >> 5;
    int wm = wid & 3, wn = wid >> 2;
    int gr = lane >> 2, gc = (lane & 3) * 2;
    int lr_a = lane & 15, lc_a = (lane >> 4) << 3;
    int lr_b = ((lane >> 4) << 3) + (lane & 7), lc_b = ((lane >> 3) & 1) << 3;
    int m0 = blockIdx.x * 64, n0 = blockIdx.y * 128;

    int ra = tid >> 2, ca = (tid & 3) * 8;

    float acc[8][4];
    #pragma unroll
    for (int i = 0; i < 8; i++)
        #pragma unroll
        for (int c = 0; c < 4; c++) acc[i][c] = 0.f;

    {
        cpa16(sptr(&sA[0][ra][ca]), &g_o[(size_t)(m0 + ra) * CC + ca]);
        cpa16(sptr(&sB[0][ra][ca]), &g_wproj[(size_t)(n0 + ra) * CC + ca]);
        cpa16(sptr(&sB[0][ra + 64][ca]), &g_wproj[(size_t)(n0 + ra + 64) * CC + ca]);
        cpcommit();
    }

    for (int kt = 0; kt < 12; kt++) {
        int buf = kt & 1;
        if (kt < 11) {
            int nb2 = buf ^ 1, kc0 = (kt + 1) * 32;
            cpa16(sptr(&sA[nb2][ra][ca]), &g_o[(size_t)(m0 + ra) * CC + kc0 + ca]);
            cpa16(sptr(&sB[nb2][ra][ca]), &g_wproj[(size_t)(n0 + ra) * CC + kc0 + ca]);
            cpa16(sptr(&sB[nb2][ra + 64][ca]), &g_wproj[(size_t)(n0 + ra + 64) * CC + kc0 + ca]);
            cpcommit();
            cpwait<1>();
        } else {
            cpwait<0>();
        }
        __syncthreads();
        #pragma unroll
        for (int kc = 0; kc < 2; kc++) {
            uint32_t af[4];
            ldsm4(af, sptr(&sA[buf][wm * 16 + lr_a][kc * 16 + lc_a]));
            #pragma unroll
            for (int np = 0; np < 4; np++) {
                uint32_t bfr[4];
                ldsm4(bfr, sptr(&sB[buf][wn * 64 + np * 16 + lr_b][kc * 16 + lc_b]));
                mma16816(acc[2 * np], af, bfr[0], bfr[1]);
                mma16816(acc[2 * np + 1], af, bfr[2], bfr[3]);
            }
        }
        __syncthreads();
    }

    float sc = a_proj_a[0] * a_proj_w[0];
    #pragma unroll
    for (int nc = 0; nc < 8; nc++)
        #pragma unroll
        for (int h2 = 0; h2 < 2; h2++) {
            int row = m0 + wm * 16 + gr + h2 * 8;
            int col = n0 + wn * 64 + nc * 8 + gc;
            float2 r2;
            r2.x = acc[nc][2 * h2] * sc + bproj[col];
            r2.y = acc[nc][2 * h2 + 1] * sc + bproj[col + 1];
            *(float2*)&out[(size_t)row * CC + col] = r2;
        }
}

// ---------------- launch ----------------
extern "C" void kernel_launch(void* const* d_in, const int* in_sizes, int n_in,
                              void* d_out, int out_size) {
    const float* x        = (const float*)d_in[0];
    const float* wqkv     = (const float*)d_in[1];
    const float* wproj    = (const float*)d_in[2];
    const float* bproj    = (const float*)d_in[3];
    const float* a_qkv_w  = (const float*)d_in[4];
    const float* a_qkv_a  = (const float*)d_in[5];
    const float* a_proj_w = (const float*)d_in[6];
    const float* a_proj_a = (const float*)d_in[7];
    const float* a_q      = (const float*)d_in[8];
    const float* a_k      = (const float*)d_in[9];
    const float* a_v      = (const float*)d_in[10];
    const float* a_attn   = (const float*)d_in[11];
    const float* a_attn2  = (const float*)d_in[12];
    float* out = (float*)d_out;

    k_quant<<<(MM * CC / 4 + 255) / 256, 256>>>(x, wqkv, wproj, a_qkv_w, a_proj_w, a_qkv_a);
    k_qkv<<<dim3(64, 9), 256>>>(a_qkv_a, a_qkv_w, a_q, a_k, a_v);
    k_attn<<<dim3(32, 12), 128>>>(a_q, a_k, a_attn, a_attn2, a_v, a_proj_a);
    k_proj<<<dim3(64, 3), 256>>>(out, bproj, a_proj_a, a_proj_w);
}